// round 5
// baseline (speedup 1.0000x reference)
#include <cuda_runtime.h>
#include <cstdint>
#include <cstddef>

// ---------------- configuration ----------------
#define THREADS 256
#define BT 32          // batch rows per CTA
#define RM 2           // rows per thread (16 row-groups x 2)

// smem strides (floats); multiples of 4 (16B alignment), ≡4 mod 32 so the
// 16-lane B-operand LDS.128 splits into two conflict-free phases.
#define LD1 116        // W1^T K=112 pad 116
#define LD2 132        // W2^T K=128
#define LD3 132        // W3^T K=128
#define LDD 68         // Wd1^T/Wd2^T K=64
#define HS  68         // h stride
#define XS  52         // xm stride (48 pad 52)
#define ZS  132        // z stride (128 pad 132)

// smem layout (float offsets)
#define O_W1T 0
#define O_W2T (O_W1T + 128*LD1)
#define O_W3T (O_W2T + 128*LD2)
#define O_WD1 (O_W3T + 64*LD3)
#define O_WD2 (O_WD1 + 64*LDD)
#define O_B1  (O_WD2 + 64*LDD)
#define O_B2  (O_B1 + 128)
#define O_B3  (O_B2 + 128)
#define O_BD1 (O_B3 + 64)
#define O_BD2 (O_BD1 + 64)
#define O_SCL (O_BD2 + 64)
#define O_H   (O_SCL + 64)
#define O_XM  (O_H + BT*HS)
#define O_Z   (O_XM + BT*XS)
#define O_IDX (O_Z + BT*ZS)              // 32 ints: per-step gather index
#define SMEM_FLOATS (O_IDX + 32)         // 230,016 bytes

// packed dual-fp32 FMA (Blackwell f32x2). d.lo += a.lo*b.lo; d.hi += a.hi*b.hi
#define FFMA2(d, a, b) asm("fma.rn.f32x2 %0, %1, %2, %0;" : "+l"(d) : "l"(a), "l"(b))

__device__ __forceinline__ float hadd2(unsigned long long p) {
    float lo, hi;
    asm("mov.b64 {%0,%1}, %2;" : "=f"(lo), "=f"(hi) : "l"(p));
    return lo + hi;
}

// Software-pipelined register-tiled GEMM fragment.
// One-quad-ahead prefetch (ping/pong a+b buffers), and within each quad all
// .x products issue before all .y products, so each accumulator's reuse
// distance is RM*CN instructions (RAW latency fully hidden).
// Register cost kept bounded: a 2*RM*4 + b 2*CN*4 + acc RM*CN*2 regs.
// NQ = K/4 must be even (true for all fragments here).
template<int K, int LDA, int LDB, int CN>
__device__ __forceinline__ void gemm_rc(const float* __restrict__ A,
                                        const float* __restrict__ Bt,
                                        unsigned long long (&acc)[RM][CN]) {
    constexpr int NQ = K / 4;
    static_assert((NQ & 1) == 0, "NQ must be even");

    ulonglong2 a0[RM], b0[CN], a1[RM], b1[CN];

#pragma unroll
    for (int r = 0; r < RM; r++)
        a0[r] = *reinterpret_cast<const ulonglong2*>(A + r*LDA);
#pragma unroll
    for (int c = 0; c < CN; c++)
        b0[c] = *reinterpret_cast<const ulonglong2*>(Bt + c*16*LDB);

#pragma unroll 1
    for (int q = 0; q < NQ; q += 2) {
        // prefetch quad q+1 while computing quad q
#pragma unroll
        for (int r = 0; r < RM; r++)
            a1[r] = *reinterpret_cast<const ulonglong2*>(A + r*LDA + (q+1)*4);
#pragma unroll
        for (int c = 0; c < CN; c++)
            b1[c] = *reinterpret_cast<const ulonglong2*>(Bt + c*16*LDB + (q+1)*4);

#pragma unroll
        for (int c = 0; c < CN; c++)
#pragma unroll
            for (int r = 0; r < RM; r++)
                FFMA2(acc[r][c], a0[r].x, b0[c].x);
#pragma unroll
        for (int c = 0; c < CN; c++)
#pragma unroll
            for (int r = 0; r < RM; r++)
                FFMA2(acc[r][c], a0[r].y, b0[c].y);

        // prefetch quad q+2 while computing quad q+1
        if (q + 2 < NQ) {
#pragma unroll
            for (int r = 0; r < RM; r++)
                a0[r] = *reinterpret_cast<const ulonglong2*>(A + r*LDA + (q+2)*4);
#pragma unroll
            for (int c = 0; c < CN; c++)
                b0[c] = *reinterpret_cast<const ulonglong2*>(Bt + c*16*LDB + (q+2)*4);
        }

#pragma unroll
        for (int c = 0; c < CN; c++)
#pragma unroll
            for (int r = 0; r < RM; r++)
                FFMA2(acc[r][c], a1[r].x, b1[c].x);
#pragma unroll
        for (int c = 0; c < CN; c++)
#pragma unroll
            for (int r = 0; r < RM; r++)
                FFMA2(acc[r][c], a1[r].y, b1[c].y);
    }
}

extern "C" __global__ void __launch_bounds__(THREADS, 1)
nsde_kernel(const float* __restrict__ x_path, const float* __restrict__ macro_path,
            const float* __restrict__ t_span, const float* __restrict__ noise,
            const float* __restrict__ W1,  const float* __restrict__ b1,
            const float* __restrict__ W2,  const float* __restrict__ b2,
            const float* __restrict__ W3,  const float* __restrict__ b3,
            const float* __restrict__ Wd1, const float* __restrict__ bd1,
            const float* __restrict__ Wd2, const float* __restrict__ bd2,
            const float* __restrict__ scale,
            const float* __restrict__ Wr1, const float* __restrict__ br1,
            const float* __restrict__ Wr2, const float* __restrict__ br2,
            float* __restrict__ out, int B, int STEPS)
{
    extern __shared__ __align__(16) float sm[];
    const int tid = threadIdx.x;
    const int cx  = tid & 15;        // 16 column groups
    const int ry  = tid >> 4;        // 16 row groups
    const int r0  = ry * RM;         // rows r0, r0+1
    const int b0  = blockIdx.x * BT;

    // ---- one-time: load + transpose weights into smem ----
    for (int i = tid; i < 112*128; i += THREADS) {
        int k = i >> 7, n = i & 127;
        sm[O_W1T + n*LD1 + k] = W1[i];
    }
    for (int i = tid; i < 128*128; i += THREADS) {
        int k = i >> 7, n = i & 127;
        sm[O_W2T + n*LD2 + k] = W2[i];
    }
    for (int i = tid; i < 128*64; i += THREADS) {
        int k = i >> 6, n = i & 63;
        sm[O_W3T + n*LD3 + k] = W3[i];
    }
    for (int i = tid; i < 64*64; i += THREADS) {
        int k = i >> 6, n = i & 63;
        sm[O_WD1 + n*LDD + k] = Wd1[i];
        sm[O_WD2 + n*LDD + k] = Wd2[i];
    }
    if (tid < 128) { sm[O_B1 + tid] = b1[tid]; sm[O_B2 + tid] = b2[tid]; }
    if (tid < 64)  {
        sm[O_B3 + tid] = b3[tid]; sm[O_BD1 + tid] = bd1[tid];
        sm[O_BD2 + tid] = bd2[tid]; sm[O_SCL + tid] = scale[tid];
    }
    for (int i = tid; i < BT*HS; i += THREADS) sm[O_H + i] = 0.0f;

    // precompute per-step gather indices once
    if (tid < STEPS) {
        float tn = t_span[tid] / t_span[STEPS];
        int idx  = (int)(tn * 255.0f);
        reinterpret_cast<int*>(sm + O_IDX)[tid] = max(0, min(idx, 255));
    }

    const float sqdt = sqrtf(0.05f);

    for (int s = 0; s < STEPS; s++) {
        // ---- prefetch this step's noise into registers (consumed at step end)
        float nz[RM][4];
#pragma unroll
        for (int r = 0; r < RM; r++)
#pragma unroll
            for (int c = 0; c < 4; c++)
                nz[r][c] = noise[((size_t)s * B + (b0 + r0 + r)) * 64 + (cx + 16*c)];

        const int idx = reinterpret_cast<const int*>(sm + O_IDX)[s];

        // ---- gather x_t (32 floats/row) and m_t (16 floats/row) ----
        for (int i = tid; i < 256; i += THREADS) {        // x: 32 rows x 8 float4
            int r = i >> 3, q = i & 7;
            const float* src = x_path + ((size_t)(b0 + r) * 256 + idx) * 32 + 4*q;
            *reinterpret_cast<float4*>(&sm[O_XM + r*XS + 4*q]) =
                *reinterpret_cast<const float4*>(src);
        }
        for (int i = tid; i < 128; i += THREADS) {        // m: 32 rows x 4 float4
            int r = i >> 2, q = i & 3;
            const float* src = macro_path + ((size_t)(b0 + r) * 256 + idx) * 16 + 4*q;
            *reinterpret_cast<float4*>(&sm[O_XM + r*XS + 32 + 4*q]) =
                *reinterpret_cast<const float4*>(src);
        }
        __syncthreads();   // xm ready; prev-step h writes & z readers drained

        // ---- GEMM1: z1 = relu([h | x | m] @ W1 + b1)  (K = 64 + 48) ----
        {
            unsigned long long acc[RM][8] = {};
            gemm_rc<64, HS, LD1, 8>(sm + O_H  + r0*HS, sm + O_W1T + cx*LD1,      acc);
            gemm_rc<48, XS, LD1, 8>(sm + O_XM + r0*XS, sm + O_W1T + cx*LD1 + 64, acc);
#pragma unroll
            for (int c = 0; c < 8; c++) {
                int col = cx + 16*c;
                float bias = sm[O_B1 + col];
#pragma unroll
                for (int r = 0; r < RM; r++)
                    sm[O_Z + (r0+r)*ZS + col] = fmaxf(hadd2(acc[r][c]) + bias, 0.0f);
            }
        }
        __syncthreads();   // z1 visible

        // ---- GEMM2: z2 = relu(z1 @ W2 + b2)  (in-place in z buffer) ----
        {
            unsigned long long acc[RM][8] = {};
            gemm_rc<128, ZS, LD2, 8>(sm + O_Z + r0*ZS, sm + O_W2T + cx*LD2, acc);
            __syncthreads();   // everyone finished READING z1 before overwrite
#pragma unroll
            for (int c = 0; c < 8; c++) {
                int col = cx + 16*c;
                float bias = sm[O_B2 + col];
#pragma unroll
                for (int r = 0; r < RM; r++)
                    sm[O_Z + (r0+r)*ZS + col] = fmaxf(hadd2(acc[r][c]) + bias, 0.0f);
            }
        }
        __syncthreads();   // z2 visible

        // ---- GEMM3: drift = z2 @ W3 + b3 (kept in regs) ----
        float drift[RM][4];
        {
            unsigned long long acc[RM][4] = {};
            gemm_rc<128, ZS, LD3, 4>(sm + O_Z + r0*ZS, sm + O_W3T + cx*LD3, acc);

            // ---- GEMMd1: zd = relu(h @ Wd1 + bd1) ----
            unsigned long long accd[RM][4] = {};
            gemm_rc<64, HS, LDD, 4>(sm + O_H + r0*HS, sm + O_WD1 + cx*LDD, accd);

#pragma unroll
            for (int c = 0; c < 4; c++) {
                int col = cx + 16*c;
                float bias3 = sm[O_B3 + col];
#pragma unroll
                for (int r = 0; r < RM; r++)
                    drift[r][c] = hadd2(acc[r][c]) + bias3;
            }
            __syncthreads();   // all reads of z2 (and h for Gd1) complete
#pragma unroll
            for (int c = 0; c < 4; c++) {
                int col = cx + 16*c;
                float biasd = sm[O_BD1 + col];
#pragma unroll
                for (int r = 0; r < RM; r++)
                    sm[O_Z + (r0+r)*ZS + col] = fmaxf(hadd2(accd[r][c]) + biasd, 0.0f);
            }
        }
        __syncthreads();   // zd visible

        // ---- GEMMd2: diff = scale * sigmoid(zd @ Wd2 + bd2); Euler update ----
        {
            unsigned long long acc[RM][4] = {};
            gemm_rc<64, ZS, LDD, 4>(sm + O_Z + r0*ZS, sm + O_WD2 + cx*LDD, acc);
#pragma unroll
            for (int c = 0; c < 4; c++) {
                int col = cx + 16*c;
                float biasd2 = sm[O_BD2 + col];
                float scl    = sm[O_SCL + col];
#pragma unroll
                for (int r = 0; r < RM; r++) {
                    float u    = hadd2(acc[r][c]) + biasd2;
                    float sig  = 1.0f / (1.0f + __expf(-u));
                    float diff = scl * sig;
                    sm[O_H + (r0+r)*HS + col] += drift[r][c]*0.05f + diff*sqdt*nz[r][c];
                }
            }
        }
        // next iteration's top-of-loop __syncthreads orders h/z for step s+1
    }
    __syncthreads();   // final h visible

    // ---- readout: z = relu(h @ Wr1 + br1); out = z @ Wr2 + br2 ----
    for (int i = tid; i < 256; i += THREADS) {   // 32 rows x 8 groups of 4 cols
        int r = i >> 3, g = i & 7;
        float z0 = br1[4*g], z1 = br1[4*g+1], z2 = br1[4*g+2], z3 = br1[4*g+3];
        const float* hrow = sm + O_H + r*HS;
#pragma unroll 4
        for (int k = 0; k < 64; k++) {
            float a = hrow[k];
            float4 w = *reinterpret_cast<const float4*>(Wr1 + k*32 + 4*g);
            z0 += a*w.x; z1 += a*w.y; z2 += a*w.z; z3 += a*w.w;
        }
        sm[O_Z + r*ZS + 4*g + 0] = fmaxf(z0, 0.0f);
        sm[O_Z + r*ZS + 4*g + 1] = fmaxf(z1, 0.0f);
        sm[O_Z + r*ZS + 4*g + 2] = fmaxf(z2, 0.0f);
        sm[O_Z + r*ZS + 4*g + 3] = fmaxf(z3, 0.0f);
    }
    __syncthreads();
    if (tid < 64) {
        int r = tid >> 1, o = tid & 1;
        float acc = br2[o];
#pragma unroll 4
        for (int k = 0; k < 32; k++)
            acc += sm[O_Z + r*ZS + k] * Wr2[2*k + o];
        out[(size_t)o * B + b0 + r] = acc;
    }
}

extern "C" void kernel_launch(void* const* d_in, const int* in_sizes, int n_in,
                              void* d_out, int out_size) {
    const float* x_path     = (const float*)d_in[0];
    const float* macro_path = (const float*)d_in[1];
    const float* t_span     = (const float*)d_in[2];
    const float* noise      = (const float*)d_in[3];
    const float* W1  = (const float*)d_in[4];
    const float* b1  = (const float*)d_in[5];
    const float* W2  = (const float*)d_in[6];
    const float* b2  = (const float*)d_in[7];
    const float* W3  = (const float*)d_in[8];
    const float* b3  = (const float*)d_in[9];
    const float* Wd1 = (const float*)d_in[10];
    const float* bd1 = (const float*)d_in[11];
    const float* Wd2 = (const float*)d_in[12];
    const float* bd2 = (const float*)d_in[13];
    const float* scale = (const float*)d_in[14];
    const float* Wr1 = (const float*)d_in[15];
    const float* br1 = (const float*)d_in[16];
    const float* Wr2 = (const float*)d_in[17];
    const float* br2 = (const float*)d_in[18];
    float* out = (float*)d_out;

    int B     = in_sizes[0] / (256 * 32);   // x_path (B, 256, 32)
    int STEPS = in_sizes[3] / (B * 64);     // noise (STEPS, B, 64)

    size_t smem_bytes = (size_t)SMEM_FLOATS * sizeof(float);
    cudaFuncSetAttribute(nsde_kernel,
                         cudaFuncAttributeMaxDynamicSharedMemorySize,
                         (int)smem_bytes);
    nsde_kernel<<<B / BT, THREADS, smem_bytes>>>(
        x_path, macro_path, t_span, noise,
        W1, b1, W2, b2, W3, b3, Wd1, bd1, Wd2, bd2,
        scale, Wr1, br1, Wr2, br2, out, B, STEPS);
}

// round 6
// speedup vs baseline: 1.1795x; 1.1795x over previous
#include <cuda_runtime.h>
#include <cstdint>
#include <cstddef>

// ---------------- configuration ----------------
#define THREADS 256
#define BT 32          // batch rows per CTA
#define RM 4           // rows per thread; 8 row-groups x 16 col-groups = 128/thread-group
// Two K-split groups of 128 threads each (warps 0-3 = group0/low-K, 4-7 = group1/high-K)

// smem strides (floats); multiples of 4 (16B alignment), ≡4 mod 32 so the
// 16-lane B-operand LDS.128 splits into conflict-free phases.
#define LD1 116        // W1^T K=112 pad 116
#define LD2 132        // W2^T K=128
#define LD3 132        // W3^T K=128
#define LDD 68         // Wd1^T/Wd2^T K=64
#define HS  68         // h stride
#define XS  52         // xm stride (48 pad 52)
#define ZS  132        // z stride (128 pad 132)

// smem layout (float offsets)
#define O_W1T 0
#define O_W2T (O_W1T + 128*LD1)
#define O_W3T (O_W2T + 128*LD2)
#define O_WD1 (O_W3T + 64*LD3)
#define O_WD2 (O_WD1 + 64*LDD)
#define O_B1  (O_WD2 + 64*LDD)
#define O_B2  (O_B1 + 128)
#define O_B3  (O_B2 + 128)
#define O_BD1 (O_B3 + 64)
#define O_BD2 (O_BD1 + 64)
#define O_SCL (O_BD2 + 64)
#define O_H   (O_SCL + 64)
#define O_XM  (O_H + BT*HS)
#define O_Z   (O_XM + BT*XS)
#define O_IDX (O_Z + BT*ZS)              // per-step gather indices
#define SMEM_FLOATS (O_IDX + 32)         // 230,016 bytes

// packed dual-fp32 FMA (Blackwell f32x2). d.lo += a.lo*b.lo; d.hi += a.hi*b.hi
#define FFMA2(d, a, b) asm("fma.rn.f32x2 %0, %1, %2, %0;" : "+l"(d) : "l"(a), "l"(b))

__device__ __forceinline__ float hadd2(unsigned long long p) {
    float lo, hi;
    asm("mov.b64 {%0,%1}, %2;" : "=f"(lo), "=f"(hi) : "l"(p));
    return lo + hi;
}

// MAC loop: A row-major [RM][K] (k-contiguous), Bt transposed weights [n][K].
// Per k-quad: all .x products, then all .y (acc reuse distance RM*CN instrs).
template<int K, int LDA, int LDB, int CN>
__device__ __forceinline__ void gemm_acc(const float* __restrict__ A,
                                         const float* __restrict__ Bt,
                                         unsigned long long (&acc)[RM][CN]) {
#pragma unroll 4
    for (int k = 0; k < K; k += 4) {
        ulonglong2 a[RM], b[CN];
#pragma unroll
        for (int r = 0; r < RM; r++)
            a[r] = *reinterpret_cast<const ulonglong2*>(A + r*LDA + k);
#pragma unroll
        for (int c = 0; c < CN; c++)
            b[c] = *reinterpret_cast<const ulonglong2*>(Bt + c*16*LDB + k);
#pragma unroll
        for (int c = 0; c < CN; c++)
#pragma unroll
            for (int r = 0; r < RM; r++)
                FFMA2(acc[r][c], a[r].x, b[c].x);
#pragma unroll
        for (int c = 0; c < CN; c++)
#pragma unroll
            for (int r = 0; r < RM; r++)
                FFMA2(acc[r][c], a[r].y, b[c].y);
    }
}

extern "C" __global__ void __launch_bounds__(THREADS, 1)
nsde_kernel(const float* __restrict__ x_path, const float* __restrict__ macro_path,
            const float* __restrict__ t_span, const float* __restrict__ noise,
            const float* __restrict__ W1,  const float* __restrict__ b1,
            const float* __restrict__ W2,  const float* __restrict__ b2,
            const float* __restrict__ W3,  const float* __restrict__ b3,
            const float* __restrict__ Wd1, const float* __restrict__ bd1,
            const float* __restrict__ Wd2, const float* __restrict__ bd2,
            const float* __restrict__ scale,
            const float* __restrict__ Wr1, const float* __restrict__ br1,
            const float* __restrict__ Wr2, const float* __restrict__ br2,
            float* __restrict__ out, int B, int STEPS)
{
    extern __shared__ __align__(16) float sm[];
    const int tid = threadIdx.x;
    const int grp = tid >> 7;        // 0 = low-K half, 1 = high-K half
    const int t   = tid & 127;
    const int cx  = t & 15;          // 16 column groups
    const int ry  = t >> 4;          // 8 row groups
    const int r0  = ry * RM;         // rows r0..r0+3
    const int b0  = blockIdx.x * BT;

    // ---- one-time: load + transpose weights into smem ----
    for (int i = tid; i < 112*128; i += THREADS) {
        int k = i >> 7, n = i & 127;
        sm[O_W1T + n*LD1 + k] = W1[i];
    }
    for (int i = tid; i < 128*128; i += THREADS) {
        int k = i >> 7, n = i & 127;
        sm[O_W2T + n*LD2 + k] = W2[i];
    }
    for (int i = tid; i < 128*64; i += THREADS) {
        int k = i >> 6, n = i & 63;
        sm[O_W3T + n*LD3 + k] = W3[i];
    }
    for (int i = tid; i < 64*64; i += THREADS) {
        int k = i >> 6, n = i & 63;
        sm[O_WD1 + n*LDD + k] = Wd1[i];
        sm[O_WD2 + n*LDD + k] = Wd2[i];
    }
    if (tid < 128) { sm[O_B1 + tid] = b1[tid]; sm[O_B2 + tid] = b2[tid]; }
    if (tid < 64)  {
        sm[O_B3 + tid] = b3[tid]; sm[O_BD1 + tid] = bd1[tid];
        sm[O_BD2 + tid] = bd2[tid]; sm[O_SCL + tid] = scale[tid];
    }
    for (int i = tid; i < BT*HS; i += THREADS) sm[O_H + i] = 0.0f;

    if (tid < STEPS) {
        float tn = t_span[tid] / t_span[STEPS];
        int idx  = (int)(tn * 255.0f);
        reinterpret_cast<int*>(sm + O_IDX)[tid] = max(0, min(idx, 255));
    }

    const float sqdt = sqrtf(0.05f);

    for (int s = 0; s < STEPS; s++) {
        // noise prefetch: only group0 consumes it (h-update finalize)
        float nz[RM][4];
        if (grp == 0) {
#pragma unroll
            for (int r = 0; r < RM; r++)
#pragma unroll
                for (int c = 0; c < 4; c++)
                    nz[r][c] = noise[((size_t)s * B + (b0 + r0 + r)) * 64 + (cx + 16*c)];
        }

        const int idx = reinterpret_cast<const int*>(sm + O_IDX)[s];

        // ---- gather x_t (32 f/row) and m_t (16 f/row) into XM ----
        for (int i = tid; i < 256; i += THREADS) {
            int r = i >> 3, q = i & 7;
            const float* src = x_path + ((size_t)(b0 + r) * 256 + idx) * 32 + 4*q;
            *reinterpret_cast<float4*>(&sm[O_XM + r*XS + 4*q]) =
                *reinterpret_cast<const float4*>(src);
        }
        for (int i = tid; i < 128; i += THREADS) {
            int r = i >> 2, q = i & 3;
            const float* src = macro_path + ((size_t)(b0 + r) * 256 + idx) * 16 + 4*q;
            *reinterpret_cast<float4*>(&sm[O_XM + r*XS + 32 + 4*q]) =
                *reinterpret_cast<const float4*>(src);
        }
        __syncthreads();   // xm ready; prev step fully drained

        // ================= GEMM1: z1 = relu([h|x|m] @ W1 + b1), N=128 =======
        {
            unsigned long long acc[RM][8] = {};
            if (grp == 0)
                gemm_acc<64, HS, LD1, 8>(sm + O_H  + r0*HS, sm + O_W1T + cx*LD1, acc);
            else
                gemm_acc<48, XS, LD1, 8>(sm + O_XM + r0*XS, sm + O_W1T + cx*LD1 + 64, acc);
            __syncthreads();                 // all source reads complete
            if (grp == 1) {
#pragma unroll
                for (int c = 0; c < 8; c++)
#pragma unroll
                    for (int r = 0; r < RM; r++)
                        sm[O_Z + (r0+r)*ZS + cx + 16*c] = hadd2(acc[r][c]);
            }
            __syncthreads();                 // partials visible
            if (grp == 0) {
#pragma unroll
                for (int c = 0; c < 8; c++) {
                    int col = cx + 16*c;
                    float bias = sm[O_B1 + col];
#pragma unroll
                    for (int r = 0; r < RM; r++) {
                        float v = sm[O_Z + (r0+r)*ZS + col] + hadd2(acc[r][c]) + bias;
                        sm[O_Z + (r0+r)*ZS + col] = fmaxf(v, 0.0f);
                    }
                }
            }
            __syncthreads();                 // z1 ready
        }

        // ================= GEMM2: z2 = relu(z1 @ W2 + b2), N=128 (in-place) =
        {
            unsigned long long acc[RM][8] = {};
            const int ko = grp ? 64 : 0;
            gemm_acc<64, ZS, LD2, 8>(sm + O_Z + r0*ZS + ko, sm + O_W2T + cx*LD2 + ko, acc);
            __syncthreads();                 // z1 reads done -> safe to overwrite
            if (grp == 1) {
#pragma unroll
                for (int c = 0; c < 8; c++)
#pragma unroll
                    for (int r = 0; r < RM; r++)
                        sm[O_Z + (r0+r)*ZS + cx + 16*c] = hadd2(acc[r][c]);
            }
            __syncthreads();
            if (grp == 0) {
#pragma unroll
                for (int c = 0; c < 8; c++) {
                    int col = cx + 16*c;
                    float bias = sm[O_B2 + col];
#pragma unroll
                    for (int r = 0; r < RM; r++) {
                        float v = sm[O_Z + (r0+r)*ZS + col] + hadd2(acc[r][c]) + bias;
                        sm[O_Z + (r0+r)*ZS + col] = fmaxf(v, 0.0f);
                    }
                }
            }
            __syncthreads();                 // z2 ready
        }

        // ================= GEMM3: drift = z2 @ W3 + b3, N=64 -> Z[64..127] ===
        {
            unsigned long long acc[RM][4] = {};
            const int ko = grp ? 64 : 0;
            gemm_acc<64, ZS, LD3, 4>(sm + O_Z + r0*ZS + ko, sm + O_W3T + cx*LD3 + ko, acc);
            __syncthreads();                 // z2 reads done
            if (grp == 1) {
#pragma unroll
                for (int c = 0; c < 4; c++)
#pragma unroll
                    for (int r = 0; r < RM; r++)
                        sm[O_Z + (r0+r)*ZS + 64 + cx + 16*c] = hadd2(acc[r][c]);
            }
            __syncthreads();
            if (grp == 0) {
#pragma unroll
                for (int c = 0; c < 4; c++) {
                    int col = cx + 16*c;
                    float bias = sm[O_B3 + col];
#pragma unroll
                    for (int r = 0; r < RM; r++)
                        sm[O_Z + (r0+r)*ZS + 64 + col] += hadd2(acc[r][c]) + bias;
                }
            }
            __syncthreads();                 // drift parked in Z[64..127]
        }

        // ================= GEMMd1: zd = relu(h @ Wd1 + bd1), N=64 -> Z[0..63]
        {
            unsigned long long acc[RM][4] = {};
            const int ko = grp ? 32 : 0;
            gemm_acc<32, HS, LDD, 4>(sm + O_H + r0*HS + ko, sm + O_WD1 + cx*LDD + ko, acc);
            __syncthreads();                 // (z2 low cols now dead)
            if (grp == 1) {
#pragma unroll
                for (int c = 0; c < 4; c++)
#pragma unroll
                    for (int r = 0; r < RM; r++)
                        sm[O_Z + (r0+r)*ZS + cx + 16*c] = hadd2(acc[r][c]);
            }
            __syncthreads();
            if (grp == 0) {
#pragma unroll
                for (int c = 0; c < 4; c++) {
                    int col = cx + 16*c;
                    float bias = sm[O_BD1 + col];
#pragma unroll
                    for (int r = 0; r < RM; r++) {
                        float v = sm[O_Z + (r0+r)*ZS + col] + hadd2(acc[r][c]) + bias;
                        sm[O_Z + (r0+r)*ZS + col] = fmaxf(v, 0.0f);
                    }
                }
            }
            __syncthreads();                 // zd ready in Z[0..63]
        }

        // ======== GEMMd2: diff = scale*sigmoid(zd@Wd2+bd2); Euler h update ==
        {
            unsigned long long acc[RM][4] = {};
            const int ko = grp ? 32 : 0;
            gemm_acc<32, ZS, LDD, 4>(sm + O_Z + r0*ZS + ko, sm + O_WD2 + cx*LDD + ko, acc);
            __syncthreads();                 // zd reads done
            if (grp == 1) {
#pragma unroll
                for (int c = 0; c < 4; c++)
#pragma unroll
                    for (int r = 0; r < RM; r++)
                        sm[O_Z + (r0+r)*ZS + cx + 16*c] = hadd2(acc[r][c]);
            }
            __syncthreads();
            if (grp == 0) {
#pragma unroll
                for (int c = 0; c < 4; c++) {
                    int col = cx + 16*c;
                    float biasd2 = sm[O_BD2 + col];
                    float scl    = sm[O_SCL + col];
#pragma unroll
                    for (int r = 0; r < RM; r++) {
                        float u    = sm[O_Z + (r0+r)*ZS + col] + hadd2(acc[r][c]) + biasd2;
                        float sig  = 1.0f / (1.0f + __expf(-u));
                        float diff = scl * sig;
                        float dft  = sm[O_Z + (r0+r)*ZS + 64 + col];
                        sm[O_H + (r0+r)*HS + col] += dft*0.05f + diff*sqdt*nz[r][c];
                    }
                }
            }
            // next step's top barrier orders h for step s+1
        }
        __syncthreads();
    }

    // ---- readout: z = relu(h @ Wr1 + br1); out = z @ Wr2 + br2 ----
    for (int i = tid; i < 256; i += THREADS) {   // 32 rows x 8 groups of 4 cols
        int r = i >> 3, g = i & 7;
        float z0 = br1[4*g], z1 = br1[4*g+1], z2 = br1[4*g+2], z3 = br1[4*g+3];
        const float* hrow = sm + O_H + r*HS;
#pragma unroll 4
        for (int k = 0; k < 64; k++) {
            float a = hrow[k];
            float4 w = *reinterpret_cast<const float4*>(Wr1 + k*32 + 4*g);
            z0 += a*w.x; z1 += a*w.y; z2 += a*w.z; z3 += a*w.w;
        }
        sm[O_Z + r*ZS + 4*g + 0] = fmaxf(z0, 0.0f);
        sm[O_Z + r*ZS + 4*g + 1] = fmaxf(z1, 0.0f);
        sm[O_Z + r*ZS + 4*g + 2] = fmaxf(z2, 0.0f);
        sm[O_Z + r*ZS + 4*g + 3] = fmaxf(z3, 0.0f);
    }
    __syncthreads();
    if (tid < 64) {
        int r = tid >> 1, o = tid & 1;
        float acc = br2[o];
#pragma unroll 4
        for (int k = 0; k < 32; k++)
            acc += sm[O_Z + r*ZS + k] * Wr2[2*k + o];
        out[(size_t)o * B + b0 + r] = acc;
    }
}

extern "C" void kernel_launch(void* const* d_in, const int* in_sizes, int n_in,
                              void* d_out, int out_size) {
    const float* x_path     = (const float*)d_in[0];
    const float* macro_path = (const float*)d_in[1];
    const float* t_span     = (const float*)d_in[2];
    const float* noise      = (const float*)d_in[3];
    const float* W1  = (const float*)d_in[4];
    const float* b1  = (const float*)d_in[5];
    const float* W2  = (const float*)d_in[6];
    const float* b2  = (const float*)d_in[7];
    const float* W3  = (const float*)d_in[8];
    const float* b3  = (const float*)d_in[9];
    const float* Wd1 = (const float*)d_in[10];
    const float* bd1 = (const float*)d_in[11];
    const float* Wd2 = (const float*)d_in[12];
    const float* bd2 = (const float*)d_in[13];
    const float* scale = (const float*)d_in[14];
    const float* Wr1 = (const float*)d_in[15];
    const float* br1 = (const float*)d_in[16];
    const float* Wr2 = (const float*)d_in[17];
    const float* br2 = (const float*)d_in[18];
    float* out = (float*)d_out;

    int B     = in_sizes[0] / (256 * 32);   // x_path (B, 256, 32)
    int STEPS = in_sizes[3] / (B * 64);     // noise (STEPS, B, 64)

    size_t smem_bytes = (size_t)SMEM_FLOATS * sizeof(float);
    cudaFuncSetAttribute(nsde_kernel,
                         cudaFuncAttributeMaxDynamicSharedMemorySize,
                         (int)smem_bytes);
    nsde_kernel<<<B / BT, THREADS, smem_bytes>>>(
        x_path, macro_path, t_span, noise,
        W1, b1, W2, b2, W3, b3, Wd1, bd1, Wd2, bd2,
        scale, Wr1, br1, Wr2, br2, out, B, STEPS);
}

// round 7
// speedup vs baseline: 1.2651x; 1.0726x over previous
#include <cuda_runtime.h>
#include <cstdint>
#include <cstddef>

// ---------------- configuration ----------------
#define THREADS 256
#define BT 32          // batch rows per CTA
#define RM 4           // rows per thread (8 row-groups x 4)
// Two N-split groups of 128 threads (warps 0-3 = low cols, 4-7 = high cols).
// Each group runs FULL K for its column half: no reduction, no partials.

// smem strides (floats); multiples of 4 (16B alignment), ≡4 mod 32.
#define LD1 116        // W1^T K=112 pad 116
#define LD2 132        // W2^T K=128
#define LD3 132        // W3^T K=128
#define LDD 68         // Wd1^T/Wd2^T K=64
#define HS  68         // h stride
#define XS  52         // xm stride (48 pad 52)
#define ZS  132        // z stride (128 pad 132)

// smem layout (float offsets)
#define O_W1T 0
#define O_W2T (O_W1T + 128*LD1)
#define O_W3T (O_W2T + 128*LD2)
#define O_WD1 (O_W3T + 64*LD3)
#define O_WD2 (O_WD1 + 64*LDD)
#define O_B1  (O_WD2 + 64*LDD)
#define O_B2  (O_B1 + 128)
#define O_B3  (O_B2 + 128)
#define O_BD1 (O_B3 + 64)
#define O_BD2 (O_BD1 + 64)
#define O_SCL (O_BD2 + 64)
#define O_H   (O_SCL + 64)
#define O_XM  (O_H + BT*HS)
#define O_Z   (O_XM + BT*XS)
#define O_IDX (O_Z + BT*ZS)              // per-step gather indices
#define SMEM_FLOATS (O_IDX + 32)

// packed dual-fp32 FMA (Blackwell f32x2). d.lo += a.lo*b.lo; d.hi += a.hi*b.hi
#define FFMA2(d, a, b) asm("fma.rn.f32x2 %0, %1, %2, %0;" : "+l"(d) : "l"(a), "l"(b))

__device__ __forceinline__ float hadd2(unsigned long long p) {
    float lo, hi;
    asm("mov.b64 {%0,%1}, %2;" : "=f"(lo), "=f"(hi) : "l"(p));
    return lo + hi;
}

// MAC loop: A row-major [RM][K] (k-contiguous), Bt transposed weights [n][K].
// Per k-quad: all .x products, then all .y (acc reuse distance RM*CN instrs).
template<int K, int LDA, int LDB, int CN>
__device__ __forceinline__ void gemm_acc(const float* __restrict__ A,
                                         const float* __restrict__ Bt,
                                         unsigned long long (&acc)[RM][CN]) {
#pragma unroll 4
    for (int k = 0; k < K; k += 4) {
        ulonglong2 a[RM], b[CN];
#pragma unroll
        for (int r = 0; r < RM; r++)
            a[r] = *reinterpret_cast<const ulonglong2*>(A + r*LDA + k);
#pragma unroll
        for (int c = 0; c < CN; c++)
            b[c] = *reinterpret_cast<const ulonglong2*>(Bt + c*16*LDB + k);
#pragma unroll
        for (int c = 0; c < CN; c++)
#pragma unroll
            for (int r = 0; r < RM; r++)
                FFMA2(acc[r][c], a[r].x, b[c].x);
#pragma unroll
        for (int c = 0; c < CN; c++)
#pragma unroll
            for (int r = 0; r < RM; r++)
                FFMA2(acc[r][c], a[r].y, b[c].y);
    }
}

extern "C" __global__ void __launch_bounds__(THREADS, 1)
nsde_kernel(const float* __restrict__ x_path, const float* __restrict__ macro_path,
            const float* __restrict__ t_span, const float* __restrict__ noise,
            const float* __restrict__ W1,  const float* __restrict__ b1,
            const float* __restrict__ W2,  const float* __restrict__ b2,
            const float* __restrict__ W3,  const float* __restrict__ b3,
            const float* __restrict__ Wd1, const float* __restrict__ bd1,
            const float* __restrict__ Wd2, const float* __restrict__ bd2,
            const float* __restrict__ scale,
            const float* __restrict__ Wr1, const float* __restrict__ br1,
            const float* __restrict__ Wr2, const float* __restrict__ br2,
            float* __restrict__ out, int B, int STEPS)
{
    extern __shared__ __align__(16) float sm[];
    const int tid = threadIdx.x;
    const int grp = tid >> 7;        // 0 = low col half, 1 = high col half
    const int t   = tid & 127;
    const int cx  = t & 15;          // 16 column groups within the half
    const int ry  = t >> 4;          // 8 row groups
    const int r0  = ry * RM;         // rows r0..r0+3
    const int b0  = blockIdx.x * BT;
    const int cb128 = 64*grp + cx;   // column base for N=128 GEMMs (c adds 16)
    const int cb64  = 32*grp + cx;   // column base for N=64 GEMMs

    // ---- one-time: load + transpose weights into smem ----
    for (int i = tid; i < 112*128; i += THREADS) {
        int k = i >> 7, n = i & 127;
        sm[O_W1T + n*LD1 + k] = W1[i];
    }
    for (int i = tid; i < 128*128; i += THREADS) {
        int k = i >> 7, n = i & 127;
        sm[O_W2T + n*LD2 + k] = W2[i];
    }
    for (int i = tid; i < 128*64; i += THREADS) {
        int k = i >> 6, n = i & 63;
        sm[O_W3T + n*LD3 + k] = W3[i];
    }
    for (int i = tid; i < 64*64; i += THREADS) {
        int k = i >> 6, n = i & 63;
        sm[O_WD1 + n*LDD + k] = Wd1[i];
        sm[O_WD2 + n*LDD + k] = Wd2[i];
    }
    if (tid < 128) { sm[O_B1 + tid] = b1[tid]; sm[O_B2 + tid] = b2[tid]; }
    if (tid < 64)  {
        sm[O_B3 + tid] = b3[tid]; sm[O_BD1 + tid] = bd1[tid];
        sm[O_BD2 + tid] = bd2[tid]; sm[O_SCL + tid] = scale[tid];
    }
    for (int i = tid; i < BT*HS; i += THREADS) sm[O_H + i] = 0.0f;

    if (tid < STEPS) {
        float tn = t_span[tid] / t_span[STEPS];
        int idx  = (int)(tn * 255.0f);
        reinterpret_cast<int*>(sm + O_IDX)[tid] = max(0, min(idx, 255));
    }

    const float sqdt = sqrtf(0.05f);

    for (int s = 0; s < STEPS; s++) {
        // ---- prefetch this step's noise (each group: its own 32 cols) ----
        float nz[RM][2];
#pragma unroll
        for (int r = 0; r < RM; r++)
#pragma unroll
            for (int c = 0; c < 2; c++)
                nz[r][c] = noise[((size_t)s * B + (b0 + r0 + r)) * 64 + (cb64 + 16*c)];

        const int idx = reinterpret_cast<const int*>(sm + O_IDX)[s];

        // ---- gather x_t (32 f/row) and m_t (16 f/row) into XM ----
        for (int i = tid; i < 256; i += THREADS) {
            int r = i >> 3, q = i & 7;
            const float* src = x_path + ((size_t)(b0 + r) * 256 + idx) * 32 + 4*q;
            *reinterpret_cast<float4*>(&sm[O_XM + r*XS + 4*q]) =
                *reinterpret_cast<const float4*>(src);
        }
        for (int i = tid; i < 128; i += THREADS) {
            int r = i >> 2, q = i & 3;
            const float* src = macro_path + ((size_t)(b0 + r) * 256 + idx) * 16 + 4*q;
            *reinterpret_cast<float4*>(&sm[O_XM + r*XS + 32 + 4*q]) =
                *reinterpret_cast<const float4*>(src);
        }
        __syncthreads();   // B0: xm ready; prev step's h/drift consumers drained

        // ==== GEMM1: z1 = relu([h|x|m] @ W1 + b1), each group 64 cols, K=112
        {
            unsigned long long acc[RM][4] = {};
            gemm_acc<64, HS, LD1, 4>(sm + O_H  + r0*HS, sm + O_W1T + cb128*LD1,      acc);
            gemm_acc<48, XS, LD1, 4>(sm + O_XM + r0*XS, sm + O_W1T + cb128*LD1 + 64, acc);
            // dest Z is dead -> epilogue needs no pre-barrier
#pragma unroll
            for (int c = 0; c < 4; c++) {
                int col = cb128 + 16*c;
                float bias = sm[O_B1 + col];
#pragma unroll
                for (int r = 0; r < RM; r++)
                    sm[O_Z + (r0+r)*ZS + col] = fmaxf(hadd2(acc[r][c]) + bias, 0.0f);
            }
        }
        __syncthreads();   // B1: z1 ready

        // ==== GEMM2: z2 = relu(z1 @ W2 + b2), in-place, K=128 ====
        {
            unsigned long long acc[RM][4] = {};
            gemm_acc<128, ZS, LD2, 4>(sm + O_Z + r0*ZS, sm + O_W2T + cb128*LD2, acc);
            __syncthreads();   // B2: all z1 reads done
#pragma unroll
            for (int c = 0; c < 4; c++) {
                int col = cb128 + 16*c;
                float bias = sm[O_B2 + col];
#pragma unroll
                for (int r = 0; r < RM; r++)
                    sm[O_Z + (r0+r)*ZS + col] = fmaxf(hadd2(acc[r][c]) + bias, 0.0f);
            }
        }
        __syncthreads();   // B3: z2 ready

        // ==== GEMM3 (drift = z2@W3+b3, K=128) + GEMMd1 (zd = relu(h@Wd1+bd1))
        {
            unsigned long long acc3[RM][2] = {};
            gemm_acc<128, ZS, LD3, 2>(sm + O_Z + r0*ZS, sm + O_W3T + cb64*LD3, acc3);
            unsigned long long accd[RM][2] = {};
            gemm_acc<64, HS, LDD, 2>(sm + O_H + r0*HS, sm + O_WD1 + cb64*LDD, accd);
            __syncthreads();   // B4: all z2 reads done -> safe to overwrite Z
#pragma unroll
            for (int c = 0; c < 2; c++) {
                int col = cb64 + 16*c;
                float b3v = sm[O_B3 + col];
                float bdv = sm[O_BD1 + col];
#pragma unroll
                for (int r = 0; r < RM; r++) {
                    sm[O_Z + (r0+r)*ZS + 64 + col] = hadd2(acc3[r][c]) + b3v;   // drift
                    sm[O_Z + (r0+r)*ZS + col] =
                        fmaxf(hadd2(accd[r][c]) + bdv, 0.0f);                    // zd
                }
            }
        }
        __syncthreads();   // B5: drift (Z[64..127]) + zd (Z[0..63]) ready

        // ==== GEMMd2: diff = scale*sigmoid(zd@Wd2+bd2); Euler h update ====
        {
            unsigned long long acc[RM][2] = {};
            gemm_acc<64, ZS, LDD, 2>(sm + O_Z + r0*ZS, sm + O_WD2 + cb64*LDD, acc);
            // epilogue writes only H (not a source of this GEMM) -> no barrier
#pragma unroll
            for (int c = 0; c < 2; c++) {
                int col = cb64 + 16*c;
                float biasd2 = sm[O_BD2 + col];
                float scl    = sm[O_SCL + col];
#pragma unroll
                for (int r = 0; r < RM; r++) {
                    float u    = hadd2(acc[r][c]) + biasd2;
                    float sig  = 1.0f / (1.0f + __expf(-u));
                    float diff = scl * sig;
                    float dft  = sm[O_Z + (r0+r)*ZS + 64 + col];
                    sm[O_H + (r0+r)*HS + col] += dft*0.05f + diff*sqdt*nz[r][c];
                }
            }
        }
        // next step's B0 orders H writes before G1 reads and XM overwrite
    }
    __syncthreads();   // final h visible

    // ---- readout: z = relu(h @ Wr1 + br1); out = z @ Wr2 + br2 ----
    for (int i = tid; i < 256; i += THREADS) {   // 32 rows x 8 groups of 4 cols
        int r = i >> 3, g = i & 7;
        float z0 = br1[4*g], z1 = br1[4*g+1], z2 = br1[4*g+2], z3 = br1[4*g+3];
        const float* hrow = sm + O_H + r*HS;
#pragma unroll 4
        for (int k = 0; k < 64; k++) {
            float a = hrow[k];
            float4 w = *reinterpret_cast<const float4*>(Wr1 + k*32 + 4*g);
            z0 += a*w.x; z1 += a*w.y; z2 += a*w.z; z3 += a*w.w;
        }
        sm[O_Z + r*ZS + 4*g + 0] = fmaxf(z0, 0.0f);
        sm[O_Z + r*ZS + 4*g + 1] = fmaxf(z1, 0.0f);
        sm[O_Z + r*ZS + 4*g + 2] = fmaxf(z2, 0.0f);
        sm[O_Z + r*ZS + 4*g + 3] = fmaxf(z3, 0.0f);
    }
    __syncthreads();
    if (tid < 64) {
        int r = tid >> 1, o = tid & 1;
        float acc = br2[o];
#pragma unroll 4
        for (int k = 0; k < 32; k++)
            acc += sm[O_Z + r*ZS + k] * Wr2[2*k + o];
        out[(size_t)o * B + b0 + r] = acc;
    }
}

extern "C" void kernel_launch(void* const* d_in, const int* in_sizes, int n_in,
                              void* d_out, int out_size) {
    const float* x_path     = (const float*)d_in[0];
    const float* macro_path = (const float*)d_in[1];
    const float* t_span     = (const float*)d_in[2];
    const float* noise      = (const float*)d_in[3];
    const float* W1  = (const float*)d_in[4];
    const float* b1  = (const float*)d_in[5];
    const float* W2  = (const float*)d_in[6];
    const float* b2  = (const float*)d_in[7];
    const float* W3  = (const float*)d_in[8];
    const float* b3  = (const float*)d_in[9];
    const float* Wd1 = (const float*)d_in[10];
    const float* bd1 = (const float*)d_in[11];
    const float* Wd2 = (const float*)d_in[12];
    const float* bd2 = (const float*)d_in[13];
    const float* scale = (const float*)d_in[14];
    const float* Wr1 = (const float*)d_in[15];
    const float* br1 = (const float*)d_in[16];
    const float* Wr2 = (const float*)d_in[17];
    const float* br2 = (const float*)d_in[18];
    float* out = (float*)d_out;

    int B     = in_sizes[0] / (256 * 32);   // x_path (B, 256, 32)
    int STEPS = in_sizes[3] / (B * 64);     // noise (STEPS, B, 64)

    size_t smem_bytes = (size_t)SMEM_FLOATS * sizeof(float);
    cudaFuncSetAttribute(nsde_kernel,
                         cudaFuncAttributeMaxDynamicSharedMemorySize,
                         (int)smem_bytes);
    nsde_kernel<<<B / BT, THREADS, smem_bytes>>>(
        x_path, macro_path, t_span, noise,
        W1, b1, W2, b2, W3, b3, Wd1, bd1, Wd2, bd2,
        scale, Wr1, br1, Wr2, br2, out, B, STEPS);
}